// round 13
// baseline (speedup 1.0000x reference)
#include <cuda_runtime.h>
#include <cuda_bf16.h>
#include <stdint.h>
#include <math.h>

// Fast path: D=512, K=128, balanced contiguous labels.
// Class split across 2 INDEPENDENT CTAs (64 rows each): wave quantization
// drops from 4/3.38=18% to 7/6.76=3.4% (2000 CTAs over 296 resident slots).
// The two halves merge IN-KERNEL via the threadFenceReduction pattern: each
// CTA writes an unnormalized partial (acc[512], Z) to device globals, and
// the LAST-arriving CTA of each class (per-class atomic counter) sums both
// partials in fixed order (deterministic), normalizes, writes the output,
// and resets the counter for the next graph replay.
// Per CTA: 8 warps x 8 rows as 4 ILP-2 pairs, warp-private 3-slot x 4KB
// cp.async ring, no block barriers in the main loop. Softmax WITHOUT
// max-subtraction: sim is a cosine in [-1,1], exp(sim) in [0.37,2.72] --
// overflow-free and mathematically identical to the max-shifted form.
#define D_MODEL 512
#define K_SHOT  128
#define SPLIT   2
#define ROWS_PC (K_SHOT / SPLIT)    // 64 rows per CTA
#define TPB     256
#define NWARPS  (TPB / 32)          // 8
#define ROWS_PW (ROWS_PC / NWARPS)  // 8 rows per warp
#define NPAIR   (ROWS_PW / 2)       // 4 pairs
#define NSLOT   3
#define ROW_F   D_MODEL
#define PAIR_F  (2 * ROW_F)         // 1024 floats
#define PAIR_BYTES (PAIR_F * 4)     // 4096 B

#define N_WAY_MAX 1000

// dynamic smem (floats): stage[8][3][1024] | z[8] | flag[1]
#define SM_STAGE_O 0
#define SM_STAGE_F (NWARPS * NSLOT * PAIR_F)   // 24576 floats = 96 KB
#define SM_Z_O    (SM_STAGE_O + SM_STAGE_F)
#define SM_FLAG_O (SM_Z_O + NWARPS)
#define SM_FLOATS (SM_FLAG_O + 1)
#define SM_BYTES  (SM_FLOATS * sizeof(float))

__device__ float g_pacc[(size_t)N_WAY_MAX * SPLIT * D_MODEL];
__device__ float g_pz[N_WAY_MAX * SPLIT];
__device__ int   g_cnt[N_WAY_MAX];   // zero-init; restored to 0 each launch

__device__ __forceinline__ void cp_async16(unsigned int saddr, const void* gptr) {
    asm volatile("cp.async.cg.shared.global [%0], [%1], 16;"
                 :: "r"(saddr), "l"(gptr));
}
#define CP_COMMIT() asm volatile("cp.async.commit_group;" ::: "memory")
#define CP_WAIT(n)  asm volatile("cp.async.wait_group %0;" :: "n"(n) : "memory")

__global__ __launch_bounds__(TPB, 2)
void proto_part_kernel(const float* __restrict__ feats,
                       const float* __restrict__ sem,
                       float* __restrict__ out)
{
    extern __shared__ float sm[];
    float* s_stage = sm + SM_STAGE_O;
    float* s_z     = sm + SM_Z_O;
    float* s_flag  = sm + SM_FLAG_O;

    const int tid  = threadIdx.x;
    const int b    = blockIdx.x;        // partial index
    const int c    = b >> 1;            // class
    const int half = b & 1;
    const int wid  = tid >> 5;
    const int lane = tid & 31;

    // this warp's 8 contiguous rows and private ring buffer
    const size_t row0 = (size_t)c * K_SHOT + (size_t)half * ROWS_PC
                      + (size_t)wid * ROWS_PW;
    const float4* fwarp = (const float4*)(feats + row0 * D_MODEL);
    float* my_stage = s_stage + (size_t)wid * NSLOT * PAIR_F;
    const unsigned int ring_base =
        (unsigned int)__cvta_generic_to_shared((void*)my_stage);

    // ---- prologue: issue pairs 0,1 into slots 0,1 (one group per pair) ----
#pragma unroll
    for (int t = 0; t < 2; t++) {
        unsigned int sbuf = ring_base + (unsigned int)(t * PAIR_BYTES);
#pragma unroll
        for (int k = 0; k < 4; k++) {
            int p = lane + 32 * k;
            cp_async16(sbuf + (unsigned int)p * 16u,
                       (const void*)(fwarp + (size_t)(2 * t) * (ROW_F / 4) + p));
            cp_async16(sbuf + 2048u + (unsigned int)p * 16u,
                       (const void*)(fwarp + (size_t)(2 * t + 1) * (ROW_F / 4) + p));
        }
        CP_COMMIT();
    }

    // ---- semantics straight to registers (L2-hot for sibling CTA) ----
    const float4* semg = (const float4*)(sem + (size_t)c * D_MODEL);
    float4 sv0 = semg[lane];
    float4 sv1 = semg[lane + 32];
    float4 sv2 = semg[lane + 64];
    float4 sv3 = semg[lane + 96];

    float ps = sv0.x*sv0.x + sv0.y*sv0.y + sv0.z*sv0.z + sv0.w*sv0.w
             + sv1.x*sv1.x + sv1.y*sv1.y + sv1.z*sv1.z + sv1.w*sv1.w
             + sv2.x*sv2.x + sv2.y*sv2.y + sv2.z*sv2.z + sv2.w*sv2.w
             + sv3.x*sv3.x + sv3.y*sv3.y + sv3.z*sv3.z + sv3.w*sv3.w;
#pragma unroll
    for (int s = 16; s > 0; s >>= 1)
        ps += __shfl_xor_sync(0xFFFFFFFFu, ps, s);
    const float inv_sn = 1.f / fmaxf(sqrtf(ps), 1e-8f);

    // ---- stream 4 pairs: acc += exp(sim)*x, two rows interleaved ----
    float Z = 0.f;
    float4 a0 = {0,0,0,0}, a1 = {0,0,0,0}, a2 = {0,0,0,0}, a3 = {0,0,0,0};

#pragma unroll
    for (int j = 0; j < NPAIR; j++) {
        if (j < NPAIR - 1) CP_WAIT(1);
        else               CP_WAIT(0);

        const float* base = my_stage + (size_t)(j % NSLOT) * PAIR_F;
        const float4* rx = (const float4*)base;
        const float4* ry = (const float4*)(base + ROW_F);
        float4 x0 = rx[lane], x1 = rx[lane + 32], x2 = rx[lane + 64], x3 = rx[lane + 96];
        float4 y0 = ry[lane], y1 = ry[lane + 32], y2 = ry[lane + 64], y3 = ry[lane + 96];

        // refill: issue pair j+2 into slot (j+2)%3
        if (j + 2 < NPAIR) {
            const int t = j + 2;
            unsigned int sbuf =
                ring_base + (unsigned int)((t % NSLOT) * PAIR_BYTES);
#pragma unroll
            for (int k = 0; k < 4; k++) {
                int p = lane + 32 * k;
                cp_async16(sbuf + (unsigned int)p * 16u,
                           (const void*)(fwarp + (size_t)(2 * t) * (ROW_F / 4) + p));
                cp_async16(sbuf + 2048u + (unsigned int)p * 16u,
                           (const void*)(fwarp + (size_t)(2 * t + 1) * (ROW_F / 4) + p));
            }
            CP_COMMIT();
        }

        float pdx = x0.x*sv0.x + x0.y*sv0.y + x0.z*sv0.z + x0.w*sv0.w
                  + x1.x*sv1.x + x1.y*sv1.y + x1.z*sv1.z + x1.w*sv1.w
                  + x2.x*sv2.x + x2.y*sv2.y + x2.z*sv2.z + x2.w*sv2.w
                  + x3.x*sv3.x + x3.y*sv3.y + x3.z*sv3.z + x3.w*sv3.w;
        float pdy = y0.x*sv0.x + y0.y*sv0.y + y0.z*sv0.z + y0.w*sv0.w
                  + y1.x*sv1.x + y1.y*sv1.y + y1.z*sv1.z + y1.w*sv1.w
                  + y2.x*sv2.x + y2.y*sv2.y + y2.z*sv2.z + y2.w*sv2.w
                  + y3.x*sv3.x + y3.y*sv3.y + y3.z*sv3.z + y3.w*sv3.w;
        float pnx = x0.x*x0.x + x0.y*x0.y + x0.z*x0.z + x0.w*x0.w
                  + x1.x*x1.x + x1.y*x1.y + x1.z*x1.z + x1.w*x1.w
                  + x2.x*x2.x + x2.y*x2.y + x2.z*x2.z + x2.w*x2.w
                  + x3.x*x3.x + x3.y*x3.y + x3.z*x3.z + x3.w*x3.w;
        float pny = y0.x*y0.x + y0.y*y0.y + y0.z*y0.z + y0.w*y0.w
                  + y1.x*y1.x + y1.y*y1.y + y1.z*y1.z + y1.w*y1.w
                  + y2.x*y2.x + y2.y*y2.y + y2.z*y2.z + y2.w*y2.w
                  + y3.x*y3.x + y3.y*y3.y + y3.z*y3.z + y3.w*y3.w;

#pragma unroll
        for (int sh = 16; sh > 0; sh >>= 1) {
            pdx += __shfl_xor_sync(0xFFFFFFFFu, pdx, sh);
            pdy += __shfl_xor_sync(0xFFFFFFFFu, pdy, sh);
            pnx += __shfl_xor_sync(0xFFFFFFFFu, pnx, sh);
            pny += __shfl_xor_sync(0xFFFFFFFFu, pny, sh);
        }

        const float simx = pdx * inv_sn / fmaxf(sqrtf(pnx), 1e-8f);
        const float simy = pdy * inv_sn / fmaxf(sqrtf(pny), 1e-8f);
        const float ex = __expf(simx);     // sim in [-1,1]: always safe
        const float ey = __expf(simy);
        Z += ex + ey;
        a0.x += ex*x0.x + ey*y0.x;  a0.y += ex*x0.y + ey*y0.y;
        a0.z += ex*x0.z + ey*y0.z;  a0.w += ex*x0.w + ey*y0.w;
        a1.x += ex*x1.x + ey*y1.x;  a1.y += ex*x1.y + ey*y1.y;
        a1.z += ex*x1.z + ey*y1.z;  a1.w += ex*x1.w + ey*y1.w;
        a2.x += ex*x2.x + ey*y2.x;  a2.y += ex*x2.y + ey*y2.y;
        a2.z += ex*x2.z + ey*y2.z;  a2.w += ex*x2.w + ey*y2.w;
        a3.x += ex*x3.x + ey*y3.x;  a3.y += ex*x3.y + ey*y3.y;
        a3.z += ex*x3.z + ey*y3.z;  a3.w += ex*x3.w + ey*y3.w;
    }

    // ---- dump warp partials into own ring region (slot 0) ----
    __syncthreads();
    float4* adst = (float4*)my_stage;
    adst[lane]      = a0;
    adst[lane + 32] = a1;
    adst[lane + 64] = a2;
    adst[lane + 96] = a3;
    if (lane == 0) s_z[wid] = Z;
    __syncthreads();

    // ---- CTA partial -> globals ----
    if (tid == 0) {
        float zt = 0.f;
#pragma unroll
        for (int w = 0; w < NWARPS; w++) zt += s_z[w];
        g_pz[b] = zt;
    }
#pragma unroll
    for (int h = 0; h < 2; h++) {
        const int col = tid + h * TPB;
        float acc = 0.f;
#pragma unroll
        for (int w = 0; w < NWARPS; w++)
            acc += s_stage[(size_t)w * NSLOT * PAIR_F + col];
        g_pacc[(size_t)b * D_MODEL + col] = acc;
    }

    // ---- last-CTA-merges (threadFenceReduction pattern) ----
    __threadfence();
    __syncthreads();
    if (tid == 0) {
        const int old = atomicAdd(&g_cnt[c], 1);
        s_flag[0] = (float)old;
    }
    __syncthreads();

    if (s_flag[0] != 0.f) {             // this CTA arrived second: merge
        __threadfence();                 // order: see peer's partials
        const float z = g_pz[2 * c] + g_pz[2 * c + 1];
        const float inv_z = 1.f / z;
#pragma unroll
        for (int h = 0; h < 2; h++) {
            const int col = tid + h * TPB;
            const float v = g_pacc[(size_t)(2 * c) * D_MODEL + col]
                          + g_pacc[(size_t)(2 * c + 1) * D_MODEL + col];
            out[(size_t)c * D_MODEL + col] = v * inv_z;
        }
        if (tid == 0) g_cnt[c] = 0;      // restore for next graph replay
    }
}

// Generic fallback (contiguous balanced labels, runtime K/D).
__global__ void proto_generic_kernel(const float* __restrict__ feats,
                                     const float* __restrict__ sem,
                                     float* __restrict__ out, int K, int D)
{
    extern __shared__ float s_simg[];  // K floats
    const int c    = blockIdx.x;
    const int wid  = threadIdx.x >> 5;
    const int lane = threadIdx.x & 31;
    const int nw   = blockDim.x >> 5;
    const float* S = sem + (size_t)c * D;

    for (int r = wid; r < K; r += nw) {
        const float* F = feats + ((size_t)c * K + r) * D;
        float pd = 0.f, pn = 0.f, ps = 0.f;
        for (int j = lane; j < D; j += 32) {
            float fv = F[j], sv = S[j];
            pd += fv * sv; pn += fv * fv; ps += sv * sv;
        }
        for (int s = 16; s > 0; s >>= 1) {
            pd += __shfl_xor_sync(0xFFFFFFFFu, pd, s);
            pn += __shfl_xor_sync(0xFFFFFFFFu, pn, s);
            ps += __shfl_xor_sync(0xFFFFFFFFu, ps, s);
        }
        if (lane == 0)
            s_simg[r] = pd / (fmaxf(sqrtf(pn), 1e-8f) * fmaxf(sqrtf(ps), 1e-8f));
    }
    __syncthreads();

    if (threadIdx.x == 0) {
        float m = -INFINITY;
        for (int r = 0; r < K; r++) m = fmaxf(m, s_simg[r]);
        float z = 0.f;
        for (int r = 0; r < K; r++) { float e = expf(s_simg[r] - m); s_simg[r] = e; z += e; }
        float inv = 1.f / z;
        for (int r = 0; r < K; r++) s_simg[r] *= inv;
    }
    __syncthreads();

    for (int j = threadIdx.x; j < D; j += blockDim.x) {
        float acc = 0.f;
        for (int r = 0; r < K; r++)
            acc += s_simg[r] * feats[((size_t)c * K + r) * D + j];
        out[(size_t)c * D + j] = acc;
    }
}

extern "C" void kernel_launch(void* const* d_in, const int* in_sizes, int n_in,
                              void* d_out, int out_size)
{
    const float* feats = (const float*)d_in[0];
    const float* sem   = (const float*)d_in[3];

    const int n_rows = in_sizes[1];
    const int D      = in_sizes[0] / n_rows;
    const int n_way  = in_sizes[3] / D;
    const int K      = n_rows / n_way;

    float* out = (float*)d_out;

    if (D == D_MODEL && K == K_SHOT && n_way <= N_WAY_MAX) {
        cudaFuncSetAttribute(proto_part_kernel,
                             cudaFuncAttributeMaxDynamicSharedMemorySize,
                             (int)SM_BYTES);
        proto_part_kernel<<<n_way * SPLIT, TPB, SM_BYTES>>>(feats, sem, out);
    } else {
        proto_generic_kernel<<<n_way, 256, K * sizeof(float)>>>(feats, sem, out, K, D);
    }
}

// round 14
// speedup vs baseline: 1.1957x; 1.1957x over previous
#include <cuda_runtime.h>
#include <cuda_bf16.h>
#include <stdint.h>
#include <math.h>

// Fast path: D=512, K=128, balanced contiguous labels.
// One CTA (128 threads, 4 warps) per class, 4 CTAs/SM (48KB smem each,
// regs capped so 4x128x124 fits the RF). Same validated ILP-2 inner loop as
// R12: each warp owns 32 contiguous rows processed as 16 pairs with fully
// interleaved reduction chains; warp-private 3-slot x 4KB cp.async ring;
// no block barriers in the main loop. 4 independently-scheduled CTAs per SM
// interleave their prologue/epilogue bubbles so DRAM stays busy.
// Softmax WITHOUT max-subtraction: sim is a cosine in [-1,1], exp(sim) in
// [0.37, 2.72] -- overflow-free, mathematically identical. Features are
// read from DRAM exactly once. Deterministic.
#define D_MODEL 512
#define K_SHOT  128
#define TPB     128
#define NWARPS  (TPB / 32)          // 4
#define ROWS_PW (K_SHOT / NWARPS)   // 32 rows per warp
#define NPAIR   (ROWS_PW / 2)       // 16 pairs
#define NSLOT   3
#define ROW_F   D_MODEL
#define PAIR_F  (2 * ROW_F)         // 1024 floats
#define PAIR_BYTES (PAIR_F * 4)     // 4096 B

// dynamic smem (floats): stage[4][3][1024] | z[4]
#define SM_STAGE_O 0
#define SM_STAGE_F (NWARPS * NSLOT * PAIR_F)   // 12288 floats = 48 KB
#define SM_Z_O    (SM_STAGE_O + SM_STAGE_F)
#define SM_FLOATS (SM_Z_O + NWARPS)
#define SM_BYTES  (SM_FLOATS * sizeof(float))

__device__ __forceinline__ void cp_async16(unsigned int saddr, const void* gptr) {
    asm volatile("cp.async.cg.shared.global [%0], [%1], 16;"
                 :: "r"(saddr), "l"(gptr));
}
#define CP_COMMIT() asm volatile("cp.async.commit_group;" ::: "memory")
#define CP_WAIT(n)  asm volatile("cp.async.wait_group %0;" :: "n"(n) : "memory")

__global__ __launch_bounds__(TPB, 4)
void proto_fast_kernel(const float* __restrict__ feats,
                       const float* __restrict__ sem,
                       float* __restrict__ out)
{
    extern __shared__ float sm[];
    float* s_stage = sm + SM_STAGE_O;
    float* s_z     = sm + SM_Z_O;

    const int tid  = threadIdx.x;
    const int c    = blockIdx.x;
    const int wid  = tid >> 5;
    const int lane = tid & 31;

    // this warp's 32 contiguous rows and private ring buffer
    const float4* fwarp =
        (const float4*)(feats + ((size_t)c * K_SHOT + (size_t)wid * ROWS_PW) * D_MODEL);
    float* my_stage = s_stage + (size_t)wid * NSLOT * PAIR_F;
    const unsigned int ring_base =
        (unsigned int)__cvta_generic_to_shared((void*)my_stage);

    // ---- prologue: issue pairs 0,1 into slots 0,1 (one group per pair) ----
#pragma unroll
    for (int t = 0; t < 2; t++) {
        unsigned int sbuf = ring_base + (unsigned int)(t * PAIR_BYTES);
#pragma unroll
        for (int k = 0; k < 4; k++) {
            int p = lane + 32 * k;
            cp_async16(sbuf + (unsigned int)p * 16u,
                       (const void*)(fwarp + (size_t)(2 * t) * (ROW_F / 4) + p));
            cp_async16(sbuf + 2048u + (unsigned int)p * 16u,
                       (const void*)(fwarp + (size_t)(2 * t + 1) * (ROW_F / 4) + p));
        }
        CP_COMMIT();
    }

    // ---- semantics straight to registers ----
    const float4* semg = (const float4*)(sem + (size_t)c * D_MODEL);
    float4 sv0 = semg[lane];
    float4 sv1 = semg[lane + 32];
    float4 sv2 = semg[lane + 64];
    float4 sv3 = semg[lane + 96];

    float ps = sv0.x*sv0.x + sv0.y*sv0.y + sv0.z*sv0.z + sv0.w*sv0.w
             + sv1.x*sv1.x + sv1.y*sv1.y + sv1.z*sv1.z + sv1.w*sv1.w
             + sv2.x*sv2.x + sv2.y*sv2.y + sv2.z*sv2.z + sv2.w*sv2.w
             + sv3.x*sv3.x + sv3.y*sv3.y + sv3.z*sv3.z + sv3.w*sv3.w;
#pragma unroll
    for (int s = 16; s > 0; s >>= 1)
        ps += __shfl_xor_sync(0xFFFFFFFFu, ps, s);
    const float inv_sn = 1.f / fmaxf(sqrtf(ps), 1e-8f);

    // ---- stream 16 pairs: acc += exp(sim)*x, two rows interleaved ----
    float Z = 0.f;
    float4 a0 = {0,0,0,0}, a1 = {0,0,0,0}, a2 = {0,0,0,0}, a3 = {0,0,0,0};

#pragma unroll 2
    for (int j = 0; j < NPAIR; j++) {
        if (j < NPAIR - 1) CP_WAIT(1);
        else               CP_WAIT(0);

        const float* base = my_stage + (size_t)(j % NSLOT) * PAIR_F;
        const float4* rx = (const float4*)base;
        const float4* ry = (const float4*)(base + ROW_F);
        float4 x0 = rx[lane], x1 = rx[lane + 32], x2 = rx[lane + 64], x3 = rx[lane + 96];
        float4 y0 = ry[lane], y1 = ry[lane + 32], y2 = ry[lane + 64], y3 = ry[lane + 96];

        // refill: issue pair j+2 into slot (j+2)%3 (read finished at iter j-1)
        if (j + 2 < NPAIR) {
            const int t = j + 2;
            unsigned int sbuf =
                ring_base + (unsigned int)((t % NSLOT) * PAIR_BYTES);
#pragma unroll
            for (int k = 0; k < 4; k++) {
                int p = lane + 32 * k;
                cp_async16(sbuf + (unsigned int)p * 16u,
                           (const void*)(fwarp + (size_t)(2 * t) * (ROW_F / 4) + p));
                cp_async16(sbuf + 2048u + (unsigned int)p * 16u,
                           (const void*)(fwarp + (size_t)(2 * t + 1) * (ROW_F / 4) + p));
            }
            CP_COMMIT();
        }

        // interleaved dot / norm partials for both rows
        float pdx = x0.x*sv0.x + x0.y*sv0.y + x0.z*sv0.z + x0.w*sv0.w
                  + x1.x*sv1.x + x1.y*sv1.y + x1.z*sv1.z + x1.w*sv1.w
                  + x2.x*sv2.x + x2.y*sv2.y + x2.z*sv2.z + x2.w*sv2.w
                  + x3.x*sv3.x + x3.y*sv3.y + x3.z*sv3.z + x3.w*sv3.w;
        float pdy = y0.x*sv0.x + y0.y*sv0.y + y0.z*sv0.z + y0.w*sv0.w
                  + y1.x*sv1.x + y1.y*sv1.y + y1.z*sv1.z + y1.w*sv1.w
                  + y2.x*sv2.x + y2.y*sv2.y + y2.z*sv2.z + y2.w*sv2.w
                  + y3.x*sv3.x + y3.y*sv3.y + y3.z*sv3.z + y3.w*sv3.w;
        float pnx = x0.x*x0.x + x0.y*x0.y + x0.z*x0.z + x0.w*x0.w
                  + x1.x*x1.x + x1.y*x1.y + x1.z*x1.z + x1.w*x1.w
                  + x2.x*x2.x + x2.y*x2.y + x2.z*x2.z + x2.w*x2.w
                  + x3.x*x3.x + x3.y*x3.y + x3.z*x3.z + x3.w*x3.w;
        float pny = y0.x*y0.x + y0.y*y0.y + y0.z*y0.z + y0.w*y0.w
                  + y1.x*y1.x + y1.y*y1.y + y1.z*y1.z + y1.w*y1.w
                  + y2.x*y2.x + y2.y*y2.y + y2.z*y2.z + y2.w*y2.w
                  + y3.x*y3.x + y3.y*y3.y + y3.z*y3.z + y3.w*y3.w;

        // 4 independent shfl trees, fully pipelined
#pragma unroll
        for (int sh = 16; sh > 0; sh >>= 1) {
            pdx += __shfl_xor_sync(0xFFFFFFFFu, pdx, sh);
            pdy += __shfl_xor_sync(0xFFFFFFFFu, pdy, sh);
            pnx += __shfl_xor_sync(0xFFFFFFFFu, pnx, sh);
            pny += __shfl_xor_sync(0xFFFFFFFFu, pny, sh);
        }

        const float simx = pdx * inv_sn / fmaxf(sqrtf(pnx), 1e-8f);
        const float simy = pdy * inv_sn / fmaxf(sqrtf(pny), 1e-8f);
        const float ex = __expf(simx);     // sim in [-1,1]: always safe
        const float ey = __expf(simy);
        Z += ex + ey;
        a0.x += ex*x0.x + ey*y0.x;  a0.y += ex*x0.y + ey*y0.y;
        a0.z += ex*x0.z + ey*y0.z;  a0.w += ex*x0.w + ey*y0.w;
        a1.x += ex*x1.x + ey*y1.x;  a1.y += ex*x1.y + ey*y1.y;
        a1.z += ex*x1.z + ey*y1.z;  a1.w += ex*x1.w + ey*y1.w;
        a2.x += ex*x2.x + ey*y2.x;  a2.y += ex*x2.y + ey*y2.y;
        a2.z += ex*x2.z + ey*y2.z;  a2.w += ex*x2.w + ey*y2.w;
        a3.x += ex*x3.x + ey*y3.x;  a3.y += ex*x3.y + ey*y3.y;
        a3.z += ex*x3.z + ey*y3.z;  a3.w += ex*x3.w + ey*y3.w;
    }

    // ---- dump warp partials into own ring region (slot 0) ----
    __syncthreads();   // all warps done consuming their rings
    float4* adst = (float4*)my_stage;
    adst[lane]      = a0;
    adst[lane + 32] = a1;
    adst[lane + 64] = a2;
    adst[lane + 96] = a3;
    if (lane == 0) s_z[wid] = Z;
    __syncthreads();

    // ---- CTA combine: plain sums, 4 cols/thread, coalesced store ----
    float zt = 0.f;
#pragma unroll
    for (int w = 0; w < NWARPS; w++) zt += s_z[w];
    const float inv_z = 1.f / zt;

#pragma unroll
    for (int h = 0; h < 4; h++) {
        const int col = tid + h * TPB;
        float acc = 0.f;
#pragma unroll
        for (int w = 0; w < NWARPS; w++)
            acc += s_stage[(size_t)w * NSLOT * PAIR_F + col];
        out[(size_t)c * D_MODEL + col] = acc * inv_z;
    }
}

// Generic fallback (contiguous balanced labels, runtime K/D).
__global__ void proto_generic_kernel(const float* __restrict__ feats,
                                     const float* __restrict__ sem,
                                     float* __restrict__ out, int K, int D)
{
    extern __shared__ float s_simg[];  // K floats
    const int c    = blockIdx.x;
    const int wid  = threadIdx.x >> 5;
    const int lane = threadIdx.x & 31;
    const int nw   = blockDim.x >> 5;
    const float* S = sem + (size_t)c * D;

    for (int r = wid; r < K; r += nw) {
        const float* F = feats + ((size_t)c * K + r) * D;
        float pd = 0.f, pn = 0.f, ps = 0.f;
        for (int j = lane; j < D; j += 32) {
            float fv = F[j], sv = S[j];
            pd += fv * sv; pn += fv * fv; ps += sv * sv;
        }
        for (int s = 16; s > 0; s >>= 1) {
            pd += __shfl_xor_sync(0xFFFFFFFFu, pd, s);
            pn += __shfl_xor_sync(0xFFFFFFFFu, pn, s);
            ps += __shfl_xor_sync(0xFFFFFFFFu, ps, s);
        }
        if (lane == 0)
            s_simg[r] = pd / (fmaxf(sqrtf(pn), 1e-8f) * fmaxf(sqrtf(ps), 1e-8f));
    }
    __syncthreads();

    if (threadIdx.x == 0) {
        float m = -INFINITY;
        for (int r = 0; r < K; r++) m = fmaxf(m, s_simg[r]);
        float z = 0.f;
        for (int r = 0; r < K; r++) { float e = expf(s_simg[r] - m); s_simg[r] = e; z += e; }
        float inv = 1.f / z;
        for (int r = 0; r < K; r++) s_simg[r] *= inv;
    }
    __syncthreads();

    for (int j = threadIdx.x; j < D; j += blockDim.x) {
        float acc = 0.f;
        for (int r = 0; r < K; r++)
            acc += s_simg[r] * feats[((size_t)c * K + r) * D + j];
        out[(size_t)c * D + j] = acc;
    }
}

extern "C" void kernel_launch(void* const* d_in, const int* in_sizes, int n_in,
                              void* d_out, int out_size)
{
    const float* feats = (const float*)d_in[0];
    const float* sem   = (const float*)d_in[3];

    const int n_rows = in_sizes[1];
    const int D      = in_sizes[0] / n_rows;
    const int n_way  = in_sizes[3] / D;
    const int K      = n_rows / n_way;

    float* out = (float*)d_out;

    if (D == D_MODEL && K == K_SHOT) {
        cudaFuncSetAttribute(proto_fast_kernel,
                             cudaFuncAttributeMaxDynamicSharedMemorySize,
                             (int)SM_BYTES);
        proto_fast_kernel<<<n_way, TPB, SM_BYTES>>>(feats, sem, out);
    } else {
        proto_generic_kernel<<<n_way, 256, K * sizeof(float)>>>(feats, sem, out, K, D);
    }
}

// round 15
// speedup vs baseline: 1.2077x; 1.0100x over previous
#include <cuda_runtime.h>
#include <cuda_bf16.h>
#include <stdint.h>
#include <math.h>

// Fast path: D=512, K=128, balanced contiguous labels.
// One CTA (64 threads, 2 warps) per class, ~24.6KB smem -> up to 9 CTAs/SM,
// so the whole 1000-CTA grid is resident in a SINGLE WAVE (ceil(1000/148)=7
// per SM): no wave boundaries, no tail. Each warp owns 64 contiguous rows
// processed as 32 ILP-2 pairs (validated R12 inner loop) through a
// warp-private 3-slot x 4KB cp.async ring; no block barriers in the main
// loop. Softmax WITHOUT max-subtraction: sim is a cosine in [-1,1], so
// exp(sim) in [0.37,2.72] -- overflow-free, mathematically identical.
// Features are read from DRAM exactly once. Deterministic.
#define D_MODEL 512
#define K_SHOT  128
#define TPB     64
#define NWARPS  (TPB / 32)          // 2
#define ROWS_PW (K_SHOT / NWARPS)   // 64 rows per warp
#define NPAIR   (ROWS_PW / 2)       // 32 pairs
#define NSLOT   3
#define ROW_F   D_MODEL
#define PAIR_F  (2 * ROW_F)         // 1024 floats
#define PAIR_BYTES (PAIR_F * 4)     // 4096 B

// dynamic smem (floats): stage[2][3][1024] | z[2]
#define SM_STAGE_O 0
#define SM_STAGE_F (NWARPS * NSLOT * PAIR_F)   // 6144 floats = 24 KB
#define SM_Z_O    (SM_STAGE_O + SM_STAGE_F)
#define SM_FLOATS (SM_Z_O + NWARPS)
#define SM_BYTES  (SM_FLOATS * sizeof(float))

__device__ __forceinline__ void cp_async16(unsigned int saddr, const void* gptr) {
    asm volatile("cp.async.cg.shared.global [%0], [%1], 16;"
                 :: "r"(saddr), "l"(gptr));
}
#define CP_COMMIT() asm volatile("cp.async.commit_group;" ::: "memory")
#define CP_WAIT(n)  asm volatile("cp.async.wait_group %0;" :: "n"(n) : "memory")

__global__ __launch_bounds__(TPB, 9)
void proto_fast_kernel(const float* __restrict__ feats,
                       const float* __restrict__ sem,
                       float* __restrict__ out)
{
    extern __shared__ float sm[];
    float* s_stage = sm + SM_STAGE_O;
    float* s_z     = sm + SM_Z_O;

    const int tid  = threadIdx.x;
    const int c    = blockIdx.x;
    const int wid  = tid >> 5;
    const int lane = tid & 31;

    // this warp's 64 contiguous rows and private ring buffer
    const float4* fwarp =
        (const float4*)(feats + ((size_t)c * K_SHOT + (size_t)wid * ROWS_PW) * D_MODEL);
    float* my_stage = s_stage + (size_t)wid * NSLOT * PAIR_F;
    const unsigned int ring_base =
        (unsigned int)__cvta_generic_to_shared((void*)my_stage);

    // ---- prologue: issue pairs 0,1 into slots 0,1 (one group per pair) ----
#pragma unroll
    for (int t = 0; t < 2; t++) {
        unsigned int sbuf = ring_base + (unsigned int)(t * PAIR_BYTES);
#pragma unroll
        for (int k = 0; k < 4; k++) {
            int p = lane + 32 * k;
            cp_async16(sbuf + (unsigned int)p * 16u,
                       (const void*)(fwarp + (size_t)(2 * t) * (ROW_F / 4) + p));
            cp_async16(sbuf + 2048u + (unsigned int)p * 16u,
                       (const void*)(fwarp + (size_t)(2 * t + 1) * (ROW_F / 4) + p));
        }
        CP_COMMIT();
    }

    // ---- semantics straight to registers ----
    const float4* semg = (const float4*)(sem + (size_t)c * D_MODEL);
    float4 sv0 = semg[lane];
    float4 sv1 = semg[lane + 32];
    float4 sv2 = semg[lane + 64];
    float4 sv3 = semg[lane + 96];

    float ps = sv0.x*sv0.x + sv0.y*sv0.y + sv0.z*sv0.z + sv0.w*sv0.w
             + sv1.x*sv1.x + sv1.y*sv1.y + sv1.z*sv1.z + sv1.w*sv1.w
             + sv2.x*sv2.x + sv2.y*sv2.y + sv2.z*sv2.z + sv2.w*sv2.w
             + sv3.x*sv3.x + sv3.y*sv3.y + sv3.z*sv3.z + sv3.w*sv3.w;
#pragma unroll
    for (int s = 16; s > 0; s >>= 1)
        ps += __shfl_xor_sync(0xFFFFFFFFu, ps, s);
    const float inv_sn = 1.f / fmaxf(sqrtf(ps), 1e-8f);

    // ---- stream 32 pairs: acc += exp(sim)*x, two rows interleaved ----
    float Z = 0.f;
    float4 a0 = {0,0,0,0}, a1 = {0,0,0,0}, a2 = {0,0,0,0}, a3 = {0,0,0,0};

#pragma unroll 2
    for (int j = 0; j < NPAIR; j++) {
        if (j < NPAIR - 1) CP_WAIT(1);
        else               CP_WAIT(0);

        const float* base = my_stage + (size_t)(j % NSLOT) * PAIR_F;
        const float4* rx = (const float4*)base;
        const float4* ry = (const float4*)(base + ROW_F);
        float4 x0 = rx[lane], x1 = rx[lane + 32], x2 = rx[lane + 64], x3 = rx[lane + 96];
        float4 y0 = ry[lane], y1 = ry[lane + 32], y2 = ry[lane + 64], y3 = ry[lane + 96];

        // refill: issue pair j+2 into slot (j+2)%3 (read finished at iter j-1)
        if (j + 2 < NPAIR) {
            const int t = j + 2;
            unsigned int sbuf =
                ring_base + (unsigned int)((t % NSLOT) * PAIR_BYTES);
#pragma unroll
            for (int k = 0; k < 4; k++) {
                int p = lane + 32 * k;
                cp_async16(sbuf + (unsigned int)p * 16u,
                           (const void*)(fwarp + (size_t)(2 * t) * (ROW_F / 4) + p));
                cp_async16(sbuf + 2048u + (unsigned int)p * 16u,
                           (const void*)(fwarp + (size_t)(2 * t + 1) * (ROW_F / 4) + p));
            }
            CP_COMMIT();
        }

        // interleaved dot / norm partials for both rows
        float pdx = x0.x*sv0.x + x0.y*sv0.y + x0.z*sv0.z + x0.w*sv0.w
                  + x1.x*sv1.x + x1.y*sv1.y + x1.z*sv1.z + x1.w*sv1.w
                  + x2.x*sv2.x + x2.y*sv2.y + x2.z*sv2.z + x2.w*sv2.w
                  + x3.x*sv3.x + x3.y*sv3.y + x3.z*sv3.z + x3.w*sv3.w;
        float pdy = y0.x*sv0.x + y0.y*sv0.y + y0.z*sv0.z + y0.w*sv0.w
                  + y1.x*sv1.x + y1.y*sv1.y + y1.z*sv1.z + y1.w*sv1.w
                  + y2.x*sv2.x + y2.y*sv2.y + y2.z*sv2.z + y2.w*sv2.w
                  + y3.x*sv3.x + y3.y*sv3.y + y3.z*sv3.z + y3.w*sv3.w;
        float pnx = x0.x*x0.x + x0.y*x0.y + x0.z*x0.z + x0.w*x0.w
                  + x1.x*x1.x + x1.y*x1.y + x1.z*x1.z + x1.w*x1.w
                  + x2.x*x2.x + x2.y*x2.y + x2.z*x2.z + x2.w*x2.w
                  + x3.x*x3.x + x3.y*x3.y + x3.z*x3.z + x3.w*x3.w;
        float pny = y0.x*y0.x + y0.y*y0.y + y0.z*y0.z + y0.w*y0.w
                  + y1.x*y1.x + y1.y*y1.y + y1.z*y1.z + y1.w*y1.w
                  + y2.x*y2.x + y2.y*y2.y + y2.z*y2.z + y2.w*y2.w
                  + y3.x*y3.x + y3.y*y3.y + y3.z*y3.z + y3.w*y3.w;

        // 4 independent shfl trees, fully pipelined
#pragma unroll
        for (int sh = 16; sh > 0; sh >>= 1) {
            pdx += __shfl_xor_sync(0xFFFFFFFFu, pdx, sh);
            pdy += __shfl_xor_sync(0xFFFFFFFFu, pdy, sh);
            pnx += __shfl_xor_sync(0xFFFFFFFFu, pnx, sh);
            pny += __shfl_xor_sync(0xFFFFFFFFu, pny, sh);
        }

        const float simx = pdx * inv_sn / fmaxf(sqrtf(pnx), 1e-8f);
        const float simy = pdy * inv_sn / fmaxf(sqrtf(pny), 1e-8f);
        const float ex = __expf(simx);     // sim in [-1,1]: always safe
        const float ey = __expf(simy);
        Z += ex + ey;
        a0.x += ex*x0.x + ey*y0.x;  a0.y += ex*x0.y + ey*y0.y;
        a0.z += ex*x0.z + ey*y0.z;  a0.w += ex*x0.w + ey*y0.w;
        a1.x += ex*x1.x + ey*y1.x;  a1.y += ex*x1.y + ey*y1.y;
        a1.z += ex*x1.z + ey*y1.z;  a1.w += ex*x1.w + ey*y1.w;
        a2.x += ex*x2.x + ey*y2.x;  a2.y += ex*x2.y + ey*y2.y;
        a2.z += ex*x2.z + ey*y2.z;  a2.w += ex*x2.w + ey*y2.w;
        a3.x += ex*x3.x + ey*y3.x;  a3.y += ex*x3.y + ey*y3.y;
        a3.z += ex*x3.z + ey*y3.z;  a3.w += ex*x3.w + ey*y3.w;
    }

    // ---- dump warp partials into own ring region (slot 0) ----
    __syncthreads();   // both warps done consuming their rings
    float4* adst = (float4*)my_stage;
    adst[lane]      = a0;
    adst[lane + 32] = a1;
    adst[lane + 64] = a2;
    adst[lane + 96] = a3;
    if (lane == 0) s_z[wid] = Z;
    __syncthreads();

    // ---- CTA combine: plain sums, 8 cols/thread, coalesced store ----
    const float inv_z = 1.f / (s_z[0] + s_z[1]);

#pragma unroll
    for (int h = 0; h < 8; h++) {
        const int col = tid + h * TPB;
        const float acc = s_stage[col]
                        + s_stage[(size_t)NSLOT * PAIR_F + col];
        out[(size_t)c * D_MODEL + col] = acc * inv_z;
    }
}

// Generic fallback (contiguous balanced labels, runtime K/D).
__global__ void proto_generic_kernel(const float* __restrict__ feats,
                                     const float* __restrict__ sem,
                                     float* __restrict__ out, int K, int D)
{
    extern __shared__ float s_simg[];  // K floats
    const int c    = blockIdx.x;
    const int wid  = threadIdx.x >> 5;
    const int lane = threadIdx.x & 31;
    const int nw   = blockDim.x >> 5;
    const float* S = sem + (size_t)c * D;

    for (int r = wid; r < K; r += nw) {
        const float* F = feats + ((size_t)c * K + r) * D;
        float pd = 0.f, pn = 0.f, ps = 0.f;
        for (int j = lane; j < D; j += 32) {
            float fv = F[j], sv = S[j];
            pd += fv * sv; pn += fv * fv; ps += sv * sv;
        }
        for (int s = 16; s > 0; s >>= 1) {
            pd += __shfl_xor_sync(0xFFFFFFFFu, pd, s);
            pn += __shfl_xor_sync(0xFFFFFFFFu, pn, s);
            ps += __shfl_xor_sync(0xFFFFFFFFu, ps, s);
        }
        if (lane == 0)
            s_simg[r] = pd / (fmaxf(sqrtf(pn), 1e-8f) * fmaxf(sqrtf(ps), 1e-8f));
    }
    __syncthreads();

    if (threadIdx.x == 0) {
        float m = -INFINITY;
        for (int r = 0; r < K; r++) m = fmaxf(m, s_simg[r]);
        float z = 0.f;
        for (int r = 0; r < K; r++) { float e = expf(s_simg[r] - m); s_simg[r] = e; z += e; }
        float inv = 1.f / z;
        for (int r = 0; r < K; r++) s_simg[r] *= inv;
    }
    __syncthreads();

    for (int j = threadIdx.x; j < D; j += blockDim.x) {
        float acc = 0.f;
        for (int r = 0; r < K; r++)
            acc += s_simg[r] * feats[((size_t)c * K + r) * D + j];
        out[(size_t)c * D + j] = acc;
    }
}

extern "C" void kernel_launch(void* const* d_in, const int* in_sizes, int n_in,
                              void* d_out, int out_size)
{
    const float* feats = (const float*)d_in[0];
    const float* sem   = (const float*)d_in[3];

    const int n_rows = in_sizes[1];
    const int D      = in_sizes[0] / n_rows;
    const int n_way  = in_sizes[3] / D;
    const int K      = n_rows / n_way;

    float* out = (float*)d_out;

    if (D == D_MODEL && K == K_SHOT) {
        cudaFuncSetAttribute(proto_fast_kernel,
                             cudaFuncAttributeMaxDynamicSharedMemorySize,
                             (int)SM_BYTES);
        proto_fast_kernel<<<n_way, TPB, SM_BYTES>>>(feats, sem, out);
    } else {
        proto_generic_kernel<<<n_way, 256, K * sizeof(float)>>>(feats, sem, out, K, D);
    }
}